// round 1
// baseline (speedup 1.0000x reference)
#include <cuda_runtime.h>
#include <cuda_bf16.h>
#include <cstdint>

#define NN 4096
#define FF 256

// ---------------- scratch (device globals; no allocations) ----------------
__device__ float g_h[NN * FF];                     // 4 MB
__device__ float g_e1[NN];
__device__ float g_e2[NN];
__device__ float g_t[NN];
__device__ float g_denom;
__device__ float g_wnode[NN];
__device__ __nv_bfloat16 g_adjb[(size_t)NN * NN];  // 32 MB
__device__ __nv_bfloat16 g_ghi[NN * FF];           // 2 MB
__device__ __nv_bfloat16 g_glo[NN * FF];           // 2 MB

// ---------------- kernel 1: h = x @ W^T + b (fp32 SIMT tiled) ----------------
// x [N, 256] row-major, W [256, 256] row-major (both K-contiguous)
__global__ __launch_bounds__(256) void gemm_h_kernel(const float* __restrict__ x,
                                                     const float* __restrict__ W,
                                                     const float* __restrict__ b) {
    __shared__ __align__(16) float xs[16][68];
    __shared__ __align__(16) float ws[16][68];
    const int t = threadIdx.x;
    const int tx = t & 15, ty = t >> 4;
    const int bm = blockIdx.x, bn = blockIdx.y;
    const int r = t >> 2, seg = t & 3;

    float acc[4][4];
#pragma unroll
    for (int i = 0; i < 4; i++)
#pragma unroll
        for (int j = 0; j < 4; j++) acc[i][j] = 0.f;

    for (int kt = 0; kt < 16; ++kt) {
        float4 xv = *(const float4*)(x + (size_t)(bm * 64 + r) * 256 + kt * 16 + seg * 4);
        float4 wv = *(const float4*)(W + (size_t)(bn * 64 + r) * 256 + kt * 16 + seg * 4);
        xs[seg * 4 + 0][r] = xv.x; xs[seg * 4 + 1][r] = xv.y;
        xs[seg * 4 + 2][r] = xv.z; xs[seg * 4 + 3][r] = xv.w;
        ws[seg * 4 + 0][r] = wv.x; ws[seg * 4 + 1][r] = wv.y;
        ws[seg * 4 + 2][r] = wv.z; ws[seg * 4 + 3][r] = wv.w;
        __syncthreads();
#pragma unroll
        for (int k = 0; k < 16; ++k) {
            float4 xa = *(const float4*)&xs[k][ty * 4];
            float4 wb = *(const float4*)&ws[k][tx * 4];
            float xr[4] = {xa.x, xa.y, xa.z, xa.w};
            float wr[4] = {wb.x, wb.y, wb.z, wb.w};
#pragma unroll
            for (int i = 0; i < 4; i++)
#pragma unroll
                for (int j = 0; j < 4; j++) acc[i][j] += xr[i] * wr[j];
        }
        __syncthreads();
    }
#pragma unroll
    for (int i = 0; i < 4; i++) {
        int row = bm * 64 + ty * 4 + i;
#pragma unroll
        for (int j = 0; j < 4; j++) {
            int col = bn * 64 + tx * 4 + j;
            g_h[(size_t)row * 256 + col] = acc[i][j] + b[col];
        }
    }
}

// ---------------- kernel 2: e1 = exp(h.w1), e2 = exp(h.w2) ----------------
__global__ __launch_bounds__(256) void a12_kernel(const float* __restrict__ att_w) {
    __shared__ float aw[512];
    const int t = threadIdx.x;
    aw[t] = att_w[t];
    aw[t + 256] = att_w[t + 256];
    __syncthreads();
    const int warp = t >> 5, lane = t & 31;
    const int row = blockIdx.x * 8 + warp;
    const float* hr = g_h + (size_t)row * 256;
    float s1 = 0.f, s2 = 0.f;
#pragma unroll
    for (int q = 0; q < 2; q++) {
        int f = lane * 8 + q * 4;
        float4 hv = *(const float4*)(hr + f);
        float4 w1 = *(const float4*)(aw + f);
        float4 w2 = *(const float4*)(aw + 256 + f);
        s1 += hv.x * w1.x + hv.y * w1.y + hv.z * w1.z + hv.w * w1.w;
        s2 += hv.x * w2.x + hv.y * w2.y + hv.z * w2.z + hv.w * w2.w;
    }
#pragma unroll
    for (int d = 16; d; d >>= 1) {
        s1 += __shfl_down_sync(0xffffffffu, s1, d);
        s2 += __shfl_down_sync(0xffffffffu, s2, d);
    }
    if (lane == 0) {
        g_e1[row] = expf(s1);
        g_e2[row] = expf(s2);
    }
}

// ---------------- kernel 3: t[i] = sum_j adj[i,j]*e2[j]; adj -> bf16 ----------------
__global__ __launch_bounds__(256) void row_stats_kernel(const int* __restrict__ adj) {
    const int r = blockIdx.x, t = threadIdx.x;
    const int4* arow = (const int4*)(adj + (size_t)r * 4096) + t * 4;
    float s = 0.f;
    __align__(16) __nv_bfloat16 ob[16];
#pragma unroll
    for (int q = 0; q < 4; q++) {
        int4 a = arow[q];
        int j = t * 16 + q * 4;
        float4 ev = *(const float4*)(g_e2 + j);
        float f0 = (a.x == 1) ? 1.f : 0.f;
        float f1 = (a.y == 1) ? 1.f : 0.f;
        float f2 = (a.z == 1) ? 1.f : 0.f;
        float f3 = (a.w == 1) ? 1.f : 0.f;
        s += f0 * ev.x + f1 * ev.y + f2 * ev.z + f3 * ev.w;
        ob[q * 4 + 0] = __float2bfloat16(f0);
        ob[q * 4 + 1] = __float2bfloat16(f1);
        ob[q * 4 + 2] = __float2bfloat16(f2);
        ob[q * 4 + 3] = __float2bfloat16(f3);
    }
    int4* dst = (int4*)(g_adjb + (size_t)r * 4096 + t * 16);
    dst[0] = ((int4*)ob)[0];
    dst[1] = ((int4*)ob)[1];
    const int lane = t & 31, warp = t >> 5;
#pragma unroll
    for (int d = 16; d; d >>= 1) s += __shfl_down_sync(0xffffffffu, s, d);
    __shared__ float wsum[8];
    if (lane == 0) wsum[warp] = s;
    __syncthreads();
    if (t == 0) {
        float tot = 0.f;
#pragma unroll
        for (int w2 = 0; w2 < 8; w2++) tot += wsum[w2];
        g_t[r] = tot;
    }
}

// ---------------- kernel 4: denom = sum_i e1[i]*t[i] ----------------
__global__ __launch_bounds__(1024) void denom_kernel() {
    __shared__ float sred[1024];
    const int t = threadIdx.x;
    float s = 0.f;
    for (int i = t; i < NN; i += 1024) s += g_e1[i] * g_t[i];
    sred[t] = s;
    __syncthreads();
    for (int d = 512; d; d >>= 1) {
        if (t < d) sred[t] += sred[t + d];
        __syncthreads();
    }
    if (t == 0) g_denom = sred[0];
}

// ---------------- kernel 5: w_node via ordered scan of first N edges ----------------
__global__ __launch_bounds__(1024) void wnode_kernel(const int* __restrict__ adj) {
    __shared__ int warp_sums[32];
    __shared__ int s_base;
    __shared__ float s_inv;
    const int t = threadIdx.x, lane = t & 31, warp = t >> 5;
    if (t == 0) {
        s_base = 0;
        s_inv = 1.f / g_denom;
    }
    __syncthreads();
    const float inv = s_inv;
    for (int r = 0; r < NN; ++r) {
        int base = s_base;
        if (base >= NN) break;
        int4 a = *(const int4*)(adj + (size_t)r * 4096 + t * 4);
        int f0 = (a.x == 1), f1 = (a.y == 1), f2 = (a.z == 1), f3 = (a.w == 1);
        int cnt = f0 + f1 + f2 + f3;
        int incl = cnt;
#pragma unroll
        for (int d = 1; d < 32; d <<= 1) {
            int v = __shfl_up_sync(0xffffffffu, incl, d);
            if (lane >= d) incl += v;
        }
        if (lane == 31) warp_sums[warp] = incl;
        __syncthreads();
        if (warp == 0) {
            int v = warp_sums[lane];
#pragma unroll
            for (int d = 1; d < 32; d <<= 1) {
                int u = __shfl_up_sync(0xffffffffu, v, d);
                if (lane >= d) v += u;
            }
            warp_sums[lane] = v;  // inclusive over warps
        }
        __syncthreads();
        int wbase = (warp == 0) ? 0 : warp_sums[warp - 1];
        int o = base + wbase + (incl - cnt);
        float er = g_e1[r];
        float4 ev = *(const float4*)(g_e2 + t * 4);
        if (f0) { if (o < NN) g_wnode[o] = er * ev.x * inv; o++; }
        if (f1) { if (o < NN) g_wnode[o] = er * ev.y * inv; o++; }
        if (f2) { if (o < NN) g_wnode[o] = er * ev.z * inv; o++; }
        if (f3) { if (o < NN) g_wnode[o] = er * ev.w * inv; o++; }
        __syncthreads();
        if (t == 0) s_base = base + warp_sums[31];
        __syncthreads();
    }
}

// ---------------- kernel 6: g = wnode .* h, split into bf16 hi/lo ----------------
__global__ __launch_bounds__(128) void g_kernel() {
    const int j = blockIdx.x, t = threadIdx.x;
    const float w = g_wnode[j];
    float2 hv = *(const float2*)(g_h + (size_t)j * 256 + t * 2);
    float p0 = w * hv.x, p1 = w * hv.y;
    __nv_bfloat16 h0 = __float2bfloat16(p0);
    __nv_bfloat16 h1 = __float2bfloat16(p1);
    __nv_bfloat16 l0 = __float2bfloat16(p0 - __bfloat162float(h0));
    __nv_bfloat16 l1 = __float2bfloat16(p1 - __bfloat162float(h1));
    __nv_bfloat162 hi; hi.x = h0; hi.y = h1;
    __nv_bfloat162 lo; lo.x = l0; lo.y = l1;
    ((__nv_bfloat162*)g_ghi)[j * 128 + t] = hi;
    ((__nv_bfloat162*)g_glo)[j * 128 + t] = lo;
}

// ---------------- mma / ldmatrix helpers ----------------
__device__ __forceinline__ void mma_bf16(float& c0, float& c1, float& c2, float& c3,
                                         uint32_t a0, uint32_t a1, uint32_t a2, uint32_t a3,
                                         uint32_t b0, uint32_t b1) {
    asm volatile(
        "mma.sync.aligned.m16n8k16.row.col.f32.bf16.bf16.f32 "
        "{%0,%1,%2,%3}, {%4,%5,%6,%7}, {%8,%9}, {%0,%1,%2,%3};\n"
        : "+f"(c0), "+f"(c1), "+f"(c2), "+f"(c3)
        : "r"(a0), "r"(a1), "r"(a2), "r"(a3), "r"(b0), "r"(b1));
}
__device__ __forceinline__ void ldsm4(uint32_t& r0, uint32_t& r1, uint32_t& r2, uint32_t& r3,
                                      uint32_t addr) {
    asm volatile("ldmatrix.sync.aligned.m8n8.x4.shared.b16 {%0,%1,%2,%3}, [%4];"
                 : "=r"(r0), "=r"(r1), "=r"(r2), "=r"(r3)
                 : "r"(addr));
}
__device__ __forceinline__ void ldsm4t(uint32_t& r0, uint32_t& r1, uint32_t& r2, uint32_t& r3,
                                       uint32_t addr) {
    asm volatile("ldmatrix.sync.aligned.m8n8.x4.trans.shared.b16 {%0,%1,%2,%3}, [%4];"
                 : "=r"(r0), "=r"(r1), "=r"(r2), "=r"(r3)
                 : "r"(addr));
}

// ---------------- kernel 7: out = relu(adjb @ (ghi + glo)) via bf16 mma ----------------
// BM=64, BN=128, BK=32, 8 warps (4 in M x 2 in N), grid (64, 2)
__global__ __launch_bounds__(256) void gemm_out_kernel(float* __restrict__ out) {
    __shared__ __align__(16) __nv_bfloat16 As[64][40];
    __shared__ __align__(16) __nv_bfloat16 Bh[32][136];
    __shared__ __align__(16) __nv_bfloat16 Bl[32][136];
    const int t = threadIdx.x;
    const int warp = t >> 5, lane = t & 31;
    const int wm = warp & 3, wn = warp >> 2;
    const int bm = blockIdx.x, bn = blockIdx.y;

    float c[8][4];
#pragma unroll
    for (int i = 0; i < 8; i++)
#pragma unroll
        for (int j = 0; j < 4; j++) c[i][j] = 0.f;

    const int ar = t >> 2, aseg = t & 3;

    for (int kt = 0; kt < 128; ++kt) {
        // stage A (adj bf16): 64x32
        int4 av = *(const int4*)(g_adjb + (size_t)(bm * 64 + ar) * 4096 + kt * 32 + aseg * 8);
        *(int4*)(&As[ar][aseg * 8]) = av;
        // stage B hi/lo: 32x128 each
#pragma unroll
        for (int c2 = 0; c2 < 2; ++c2) {
            int ch = t + c2 * 256;
            int br = ch >> 4, bseg = ch & 15;
            size_t go = (size_t)(kt * 32 + br) * 256 + bn * 128 + bseg * 8;
            *(int4*)(&Bh[br][bseg * 8]) = *(const int4*)(g_ghi + go);
            *(int4*)(&Bl[br][bseg * 8]) = *(const int4*)(g_glo + go);
        }
        __syncthreads();
#pragma unroll
        for (int kk = 0; kk < 2; ++kk) {
            uint32_t a0, a1, a2, a3;
            {
                int row = wm * 16 + (lane & 15);
                int col = kk * 16 + ((lane >> 4) << 3);
                uint32_t addr = (uint32_t)__cvta_generic_to_shared(&As[row][col]);
                ldsm4(a0, a1, a2, a3, addr);
            }
#pragma unroll
            for (int ng = 0; ng < 4; ++ng) {
                int krow = kk * 16 + (lane & 15);
                int col = wn * 64 + ng * 16 + ((lane >> 4) << 3);
                uint32_t b0, b1, b2, b3;
                uint32_t addr = (uint32_t)__cvta_generic_to_shared(&Bh[krow][col]);
                ldsm4t(b0, b1, b2, b3, addr);
                mma_bf16(c[ng * 2][0], c[ng * 2][1], c[ng * 2][2], c[ng * 2][3],
                         a0, a1, a2, a3, b0, b1);
                mma_bf16(c[ng * 2 + 1][0], c[ng * 2 + 1][1], c[ng * 2 + 1][2], c[ng * 2 + 1][3],
                         a0, a1, a2, a3, b2, b3);
                addr = (uint32_t)__cvta_generic_to_shared(&Bl[krow][col]);
                ldsm4t(b0, b1, b2, b3, addr);
                mma_bf16(c[ng * 2][0], c[ng * 2][1], c[ng * 2][2], c[ng * 2][3],
                         a0, a1, a2, a3, b0, b1);
                mma_bf16(c[ng * 2 + 1][0], c[ng * 2 + 1][1], c[ng * 2 + 1][2], c[ng * 2 + 1][3],
                         a0, a1, a2, a3, b2, b3);
            }
        }
        __syncthreads();
    }
    // epilogue: relu + store
    const int g = lane >> 2, tg = lane & 3;
#pragma unroll
    for (int nf = 0; nf < 8; ++nf) {
        int col = bn * 128 + wn * 64 + nf * 8 + tg * 2;
        int row0 = bm * 64 + wm * 16 + g;
        float2 v0;
        v0.x = fmaxf(c[nf][0], 0.f);
        v0.y = fmaxf(c[nf][1], 0.f);
        *(float2*)(out + (size_t)row0 * 256 + col) = v0;
        float2 v1;
        v1.x = fmaxf(c[nf][2], 0.f);
        v1.y = fmaxf(c[nf][3], 0.f);
        *(float2*)(out + (size_t)(row0 + 8) * 256 + col) = v1;
    }
}

// ---------------- launch ----------------
extern "C" void kernel_launch(void* const* d_in, const int* in_sizes, int n_in,
                              void* d_out, int out_size) {
    const float* x = (const float*)d_in[0];
    const int* adj = (const int*)d_in[1];
    const float* W = (const float*)d_in[2];
    const float* b = (const float*)d_in[3];
    const float* att_w = (const float*)d_in[4];
    // att_b (d_in[5]) cancels in the softmax ratio; unused.
    float* out = (float*)d_out;

    gemm_h_kernel<<<dim3(64, 4), 256>>>(x, W, b);
    a12_kernel<<<512, 256>>>(att_w);
    row_stats_kernel<<<4096, 256>>>(adj);
    denom_kernel<<<1, 1024>>>();
    wnode_kernel<<<1, 1024>>>(adj);
    g_kernel<<<4096, 128>>>();
    gemm_out_kernel<<<dim3(64, 2), 256>>>(out);
}

// round 3
// speedup vs baseline: 1.9505x; 1.9505x over previous
#include <cuda_runtime.h>
#include <cuda_fp16.h>
#include <cstdint>

#define NN 4096
#define FF 256

// ---------------- scratch (device globals; no allocations) ----------------
__device__ float g_h[NN * FF];                    // 4 MB fp32 h
__device__ float g_e1[NN];
__device__ float g_e2[NN];
__device__ float g_t[NN];
__device__ float g_wnode[NN];
__device__ unsigned int g_hmax_bits;              // max |h| (float bits, >=0)
__device__ float g_S;                             // fp16 scale
__device__ float g_invS;
__device__ __half g_adjh[(size_t)NN * NN];        // 32 MB  adj as fp16 [4096][4096]
__device__ __half g_gh[(size_t)NN * FF];          // 2 MB   S * wnode_j * h[j][n], fp16
__device__ float g_part[4 * (size_t)NN * FF];     // 16 MB  split-K partials

// ---------------- kernel 1: h = x @ W^T + b (fp32 SIMT tiled) ----------------
__global__ __launch_bounds__(256) void gemm_h_kernel(const float* __restrict__ x,
                                                     const float* __restrict__ W,
                                                     const float* __restrict__ b) {
    __shared__ __align__(16) float xs[16][68];
    __shared__ __align__(16) float ws[16][68];
    const int t = threadIdx.x;
    const int tx = t & 15, ty = t >> 4;
    const int bm = blockIdx.x, bn = blockIdx.y;
    const int r = t >> 2, seg = t & 3;

    float acc[4][4];
#pragma unroll
    for (int i = 0; i < 4; i++)
#pragma unroll
        for (int j = 0; j < 4; j++) acc[i][j] = 0.f;

    for (int kt = 0; kt < 16; ++kt) {
        float4 xv = *(const float4*)(x + (size_t)(bm * 64 + r) * 256 + kt * 16 + seg * 4);
        float4 wv = *(const float4*)(W + (size_t)(bn * 64 + r) * 256 + kt * 16 + seg * 4);
        xs[seg * 4 + 0][r] = xv.x; xs[seg * 4 + 1][r] = xv.y;
        xs[seg * 4 + 2][r] = xv.z; xs[seg * 4 + 3][r] = xv.w;
        ws[seg * 4 + 0][r] = wv.x; ws[seg * 4 + 1][r] = wv.y;
        ws[seg * 4 + 2][r] = wv.z; ws[seg * 4 + 3][r] = wv.w;
        __syncthreads();
#pragma unroll
        for (int k = 0; k < 16; ++k) {
            float4 xa = *(const float4*)&xs[k][ty * 4];
            float4 wb = *(const float4*)&ws[k][tx * 4];
            float xr[4] = {xa.x, xa.y, xa.z, xa.w};
            float wr[4] = {wb.x, wb.y, wb.z, wb.w};
#pragma unroll
            for (int i = 0; i < 4; i++)
#pragma unroll
                for (int j = 0; j < 4; j++) acc[i][j] += xr[i] * wr[j];
        }
        __syncthreads();
    }
#pragma unroll
    for (int i = 0; i < 4; i++) {
        int row = bm * 64 + ty * 4 + i;
#pragma unroll
        for (int j = 0; j < 4; j++) {
            int col = bn * 64 + tx * 4 + j;
            g_h[(size_t)row * 256 + col] = acc[i][j] + b[col];
        }
    }
}

// ---------------- kernel 2: e1/e2 = exp(h.w1/2); also global max|h| ----------------
__global__ __launch_bounds__(256) void a12_kernel(const float* __restrict__ att_w) {
    __shared__ float aw[512];
    const int t = threadIdx.x;
    aw[t] = att_w[t];
    aw[t + 256] = att_w[t + 256];
    __syncthreads();
    const int warp = t >> 5, lane = t & 31;
    const int row = blockIdx.x * 8 + warp;
    const float* hr = g_h + (size_t)row * 256;
    float s1 = 0.f, s2 = 0.f, hm = 0.f;
#pragma unroll
    for (int q = 0; q < 2; q++) {
        int f = lane * 8 + q * 4;
        float4 hv = *(const float4*)(hr + f);
        float4 w1 = *(const float4*)(aw + f);
        float4 w2 = *(const float4*)(aw + 256 + f);
        s1 += hv.x * w1.x + hv.y * w1.y + hv.z * w1.z + hv.w * w1.w;
        s2 += hv.x * w2.x + hv.y * w2.y + hv.z * w2.z + hv.w * w2.w;
        hm = fmaxf(hm, fmaxf(fmaxf(fabsf(hv.x), fabsf(hv.y)),
                             fmaxf(fabsf(hv.z), fabsf(hv.w))));
    }
#pragma unroll
    for (int d = 16; d; d >>= 1) {
        s1 += __shfl_down_sync(0xffffffffu, s1, d);
        s2 += __shfl_down_sync(0xffffffffu, s2, d);
        hm = fmaxf(hm, __shfl_down_sync(0xffffffffu, hm, d));
    }
    if (lane == 0) {
        g_e1[row] = expf(s1);
        g_e2[row] = expf(s2);
        atomicMax(&g_hmax_bits, __float_as_uint(hm));  // |h|>=0: uint order == float order
    }
}

// ---------------- kernel 3: t[i] = sum_j adj[i,j]*e2[j]; adj -> fp16 ----------------
__global__ __launch_bounds__(256) void row_stats_kernel(const int* __restrict__ adj) {
    const int r = blockIdx.x, t = threadIdx.x;
    const int4* arow = (const int4*)(adj + (size_t)r * 4096) + t * 4;
    float s = 0.f;
    __align__(16) __half ob[16];
#pragma unroll
    for (int q = 0; q < 4; q++) {
        int4 a = arow[q];
        int j = t * 16 + q * 4;
        float4 ev = *(const float4*)(g_e2 + j);
        float f0 = (a.x == 1) ? 1.f : 0.f;
        float f1 = (a.y == 1) ? 1.f : 0.f;
        float f2 = (a.z == 1) ? 1.f : 0.f;
        float f3 = (a.w == 1) ? 1.f : 0.f;
        s += f0 * ev.x + f1 * ev.y + f2 * ev.z + f3 * ev.w;
        ob[q * 4 + 0] = __float2half(f0);
        ob[q * 4 + 1] = __float2half(f1);
        ob[q * 4 + 2] = __float2half(f2);
        ob[q * 4 + 3] = __float2half(f3);
    }
    int4* dst = (int4*)(g_adjh + (size_t)r * 4096 + t * 16);
    dst[0] = ((int4*)ob)[0];
    dst[1] = ((int4*)ob)[1];
    const int lane = t & 31, warp = t >> 5;
#pragma unroll
    for (int d = 16; d; d >>= 1) s += __shfl_down_sync(0xffffffffu, s, d);
    __shared__ float wsum[8];
    if (lane == 0) wsum[warp] = s;
    __syncthreads();
    if (t == 0) {
        float tot = 0.f;
#pragma unroll
        for (int w2 = 0; w2 < 8; w2++) tot += wsum[w2];
        g_t[r] = tot;
    }
}

// ---------------- kernel 4: denom + w_node ordered scan + scale S ----------------
__global__ __launch_bounds__(1024) void wnode_kernel(const int* __restrict__ adj) {
    __shared__ int warp_sums[32];
    __shared__ float redf[32];
    __shared__ int s_base;
    __shared__ float s_inv;
    const int t = threadIdx.x, lane = t & 31, warp = t >> 5;

    // denom = sum_i e1[i] * t[i]
    float sd = 0.f;
    for (int i = t; i < NN; i += 1024) sd += g_e1[i] * g_t[i];
#pragma unroll
    for (int d = 16; d; d >>= 1) sd += __shfl_down_sync(0xffffffffu, sd, d);
    if (lane == 0) redf[warp] = sd;
    __syncthreads();
    if (warp == 0) {
        float v = redf[lane];
#pragma unroll
        for (int d = 16; d; d >>= 1) v += __shfl_down_sync(0xffffffffu, v, d);
        if (lane == 0) {
            s_inv = 1.f / v;
            s_base = 0;
        }
    }
    __syncthreads();
    const float inv = s_inv;

    for (int r = 0; r < NN; ++r) {
        int base = s_base;
        if (base >= NN) break;
        int4 a = *(const int4*)(adj + (size_t)r * 4096 + t * 4);
        int f0 = (a.x == 1), f1 = (a.y == 1), f2 = (a.z == 1), f3 = (a.w == 1);
        int cnt = f0 + f1 + f2 + f3;
        int incl = cnt;
#pragma unroll
        for (int d = 1; d < 32; d <<= 1) {
            int v = __shfl_up_sync(0xffffffffu, incl, d);
            if (lane >= d) incl += v;
        }
        if (lane == 31) warp_sums[warp] = incl;
        __syncthreads();
        if (warp == 0) {
            int v = warp_sums[lane];
#pragma unroll
            for (int d = 1; d < 32; d <<= 1) {
                int u = __shfl_up_sync(0xffffffffu, v, d);
                if (lane >= d) v += u;
            }
            warp_sums[lane] = v;
        }
        __syncthreads();
        int wbase = (warp == 0) ? 0 : warp_sums[warp - 1];
        int o = base + wbase + (incl - cnt);
        float er = g_e1[r];
        float4 ev = *(const float4*)(g_e2 + t * 4);
        if (f0) { if (o < NN) g_wnode[o] = er * ev.x * inv; o++; }
        if (f1) { if (o < NN) g_wnode[o] = er * ev.y * inv; o++; }
        if (f2) { if (o < NN) g_wnode[o] = er * ev.z * inv; o++; }
        if (f3) { if (o < NN) g_wnode[o] = er * ev.w * inv; o++; }
        __syncthreads();
        if (t == 0) s_base = base + warp_sums[31];
        __syncthreads();
    }

    // scale S = 4096 / (max w * max|h|)
    __syncthreads();
    float wm = 0.f;
    for (int i = t; i < NN; i += 1024) wm = fmaxf(wm, g_wnode[i]);
#pragma unroll
    for (int d = 16; d; d >>= 1) wm = fmaxf(wm, __shfl_down_sync(0xffffffffu, wm, d));
    if (lane == 0) redf[warp] = wm;
    __syncthreads();
    if (warp == 0) {
        float v = redf[lane];
#pragma unroll
        for (int d = 16; d; d >>= 1) v = fmaxf(v, __shfl_down_sync(0xffffffffu, v, d));
        if (lane == 0) {
            float hmax = __uint_as_float(g_hmax_bits);
            float denom2 = v * hmax;
            g_S = 4096.f / denom2;
            g_invS = denom2 * (1.f / 4096.f);
        }
    }
}

// ---------------- kernel 5: g = S * wnode .* h -> fp16 [4096][256] ----------------
__global__ __launch_bounds__(128) void gscale_kernel() {
    const int j = blockIdx.x, t = threadIdx.x;
    const float ws = g_wnode[j] * g_S;
    float2 hv = *(const float2*)(g_h + (size_t)j * 256 + t * 2);
    __half2 o;
    o.x = __float2half(ws * hv.x);
    o.y = __float2half(ws * hv.y);
    ((__half2*)g_gh)[j * 128 + t] = o;
}

// ---------------- mma / ldmatrix / cp.async helpers ----------------
__device__ __forceinline__ void mma_f16(float& c0, float& c1, float& c2, float& c3,
                                        uint32_t a0, uint32_t a1, uint32_t a2, uint32_t a3,
                                        uint32_t b0, uint32_t b1) {
    asm volatile(
        "mma.sync.aligned.m16n8k16.row.col.f32.f16.f16.f32 "
        "{%0,%1,%2,%3}, {%4,%5,%6,%7}, {%8,%9}, {%0,%1,%2,%3};\n"
        : "+f"(c0), "+f"(c1), "+f"(c2), "+f"(c3)
        : "r"(a0), "r"(a1), "r"(a2), "r"(a3), "r"(b0), "r"(b1));
}
__device__ __forceinline__ void ldsm4(uint32_t& r0, uint32_t& r1, uint32_t& r2, uint32_t& r3,
                                      uint32_t addr) {
    asm volatile("ldmatrix.sync.aligned.m8n8.x4.shared.b16 {%0,%1,%2,%3}, [%4];"
                 : "=r"(r0), "=r"(r1), "=r"(r2), "=r"(r3)
                 : "r"(addr));
}
__device__ __forceinline__ void ldsm4t(uint32_t& r0, uint32_t& r1, uint32_t& r2, uint32_t& r3,
                                       uint32_t addr) {
    asm volatile("ldmatrix.sync.aligned.m8n8.x4.trans.shared.b16 {%0,%1,%2,%3}, [%4];"
                 : "=r"(r0), "=r"(r1), "=r"(r2), "=r"(r3)
                 : "r"(addr));
}
__device__ __forceinline__ void cp16(uint32_t dst, const void* src) {
    asm volatile("cp.async.cg.shared.global [%0], [%1], 16;" :: "r"(dst), "l"(src));
}
#define CP_COMMIT() asm volatile("cp.async.commit_group;" ::: "memory")
#define CP_WAIT2() asm volatile("cp.async.wait_group 2;" ::: "memory")

// ---------------- kernel 6: HMMA GEMM: part[split] = adjh[mtile] @ g ----------------
// BM=128, BN=256(full), BK=64, splitK=4, 512 threads (16 warps: 4M x 4N),
// 3-stage cp.async pipeline. grid (32 m-tiles, 4 k-splits).
#define A_STRIDE 72    // halves per A smem row (128 rows)
#define B_STRIDE 264   // halves per B smem row (64 rows)
#define STAGE_HALVES (128 * A_STRIDE + 64 * B_STRIDE)   // 9216 + 16896 = 26112
#define SMEM_DYN (3 * STAGE_HALVES * 2 + 32)

__global__ __launch_bounds__(512, 1) void gemm_out_hmma_kernel() {
    extern __shared__ __align__(16) __half smem[];
    const int t = threadIdx.x;
    const int warp = t >> 5, lane = t & 31;
    const int wm = warp & 3, wn = warp >> 2;
    const int m0 = blockIdx.x * 128;
    const int kbase = blockIdx.y * 1024;

    __half* As[3];
    __half* Bs[3];
#pragma unroll
    for (int s = 0; s < 3; s++) {
        As[s] = smem + s * STAGE_HALVES;
        Bs[s] = As[s] + 128 * A_STRIDE;
    }

    float c[2][8][4];
#pragma unroll
    for (int i = 0; i < 2; i++)
#pragma unroll
        for (int j = 0; j < 8; j++)
#pragma unroll
            for (int q = 0; q < 4; q++) c[i][j][q] = 0.f;

    // ---- stage loader: A 128x64 (1024 chunks), B 64x256 (2048 chunks), 6/thread ----
    auto load_stage = [&](int slot, int kt) {
        const int k0 = kbase + kt * 64;
        uint32_t abase = (uint32_t)__cvta_generic_to_shared(As[slot]);
        uint32_t bbase = (uint32_t)__cvta_generic_to_shared(Bs[slot]);
#pragma unroll
        for (int i = 0; i < 2; i++) {  // A: 1024 chunks
            int q = t + i * 512;
            int row = q >> 3, seg = q & 7;
            cp16(abase + (row * A_STRIDE + seg * 8) * 2,
                 g_adjh + (size_t)(m0 + row) * 4096 + k0 + seg * 8);
        }
#pragma unroll
        for (int i = 0; i < 4; i++) {  // B: 2048 chunks
            int q = t + i * 512;
            int row = q >> 5, seg = q & 31;
            cp16(bbase + (row * B_STRIDE + seg * 8) * 2,
                 g_gh + (size_t)(k0 + row) * 256 + seg * 8);
        }
        CP_COMMIT();
    };

    load_stage(0, 0);
    load_stage(1, 1);
    load_stage(2, 2);

    for (int kt = 0; kt < 16; ++kt) {
        const int slot = kt % 3;
        CP_WAIT2();
        __syncthreads();
        const __half* a_s = As[slot];
        const __half* b_s = Bs[slot];
#pragma unroll
        for (int ks = 0; ks < 4; ++ks) {
            uint32_t a[2][4];
#pragma unroll
            for (int mi = 0; mi < 2; ++mi) {
                int row = wm * 32 + mi * 16 + (lane & 15);
                int col = ks * 16 + ((lane >> 4) << 3);
                uint32_t addr =
                    (uint32_t)__cvta_generic_to_shared(a_s + row * A_STRIDE + col);
                ldsm4(a[mi][0], a[mi][1], a[mi][2], a[mi][3], addr);
            }
#pragma unroll
            for (int ng = 0; ng < 4; ++ng) {
                int krow = ks * 16 + (lane & 15);
                int col = wn * 64 + ng * 16 + ((lane >> 4) << 3);
                uint32_t b0, b1, b2, b3;
                uint32_t addr =
                    (uint32_t)__cvta_generic_to_shared(b_s + krow * B_STRIDE + col);
                ldsm4t(b0, b1, b2, b3, addr);
#pragma unroll
                for (int mi = 0; mi < 2; ++mi) {
                    mma_f16(c[mi][ng * 2][0], c[mi][ng * 2][1],
                            c[mi][ng * 2][2], c[mi][ng * 2][3],
                            a[mi][0], a[mi][1], a[mi][2], a[mi][3], b0, b1);
                    mma_f16(c[mi][ng * 2 + 1][0], c[mi][ng * 2 + 1][1],
                            c[mi][ng * 2 + 1][2], c[mi][ng * 2 + 1][3],
                            a[mi][0], a[mi][1], a[mi][2], a[mi][3], b2, b3);
                }
            }
        }
        __syncthreads();
        if (kt + 3 < 16) load_stage(slot, kt + 3);
        CP_COMMIT();  // empty group when no load: keeps wait_group count uniform
    }

    // epilogue: fp32 partials
    float* dst = g_part + (size_t)blockIdx.y * NN * FF;
    const int g = lane >> 2, tg = lane & 3;
#pragma unroll
    for (int mi = 0; mi < 2; ++mi) {
        int row0 = m0 + wm * 32 + mi * 16 + g;
#pragma unroll
        for (int nb = 0; nb < 8; ++nb) {
            int col = wn * 64 + nb * 8 + tg * 2;
            float2 v0 = {c[mi][nb][0], c[mi][nb][1]};
            float2 v1 = {c[mi][nb][2], c[mi][nb][3]};
            *(float2*)(dst + (size_t)row0 * 256 + col) = v0;
            *(float2*)(dst + (size_t)(row0 + 8) * 256 + col) = v1;
        }
    }
}

// ---------------- kernel 7: out = relu(sum partials) * invS ----------------
__global__ __launch_bounds__(256) void relu_sum_kernel(float* __restrict__ out) {
    const float invS = g_invS;
    const size_t idx = (size_t)(blockIdx.x * 256 + threadIdx.x) * 4;
    float4 a = *(const float4*)(g_part + idx);
    float4 b = *(const float4*)(g_part + (size_t)NN * FF + idx);
    float4 c = *(const float4*)(g_part + 2 * (size_t)NN * FF + idx);
    float4 d = *(const float4*)(g_part + 3 * (size_t)NN * FF + idx);
    float4 v;
    v.x = fmaxf(a.x + b.x + c.x + d.x, 0.f) * invS;
    v.y = fmaxf(a.y + b.y + c.y + d.y, 0.f) * invS;
    v.z = fmaxf(a.z + b.z + c.z + d.z, 0.f) * invS;
    v.w = fmaxf(a.w + b.w + c.w + d.w, 0.f) * invS;
    *(float4*)(out + idx) = v;
}

// ---------------- launch ----------------
extern "C" void kernel_launch(void* const* d_in, const int* in_sizes, int n_in,
                              void* d_out, int out_size) {
    const float* x = (const float*)d_in[0];
    const int* adj = (const int*)d_in[1];
    const float* W = (const float*)d_in[2];
    const float* b = (const float*)d_in[3];
    const float* att_w = (const float*)d_in[4];
    // att_b cancels in the softmax ratio; unused.
    float* out = (float*)d_out;

    static bool attr_set = false;
    if (!attr_set) {
        cudaFuncSetAttribute(gemm_out_hmma_kernel,
                             cudaFuncAttributeMaxDynamicSharedMemorySize, SMEM_DYN);
        attr_set = true;
    }

    gemm_h_kernel<<<dim3(64, 4), 256>>>(x, W, b);
    a12_kernel<<<512, 256>>>(att_w);
    row_stats_kernel<<<4096, 256>>>(adj);
    wnode_kernel<<<1, 1024>>>(adj);
    gscale_kernel<<<4096, 128>>>();
    gemm_out_hmma_kernel<<<dim3(32, 4), 512, SMEM_DYN>>>();
    relu_sum_kernel<<<1024, 256>>>(out);
}